// round 15
// baseline (speedup 1.0000x reference)
#include <cuda_runtime.h>
#include <cuda_fp16.h>
#include <cstdint>

// Problem shape (fixed by the dataset)
#define Bv  4
#define Cv  64
#define Hv  384
#define Wv  768
#define HWv (Hv * Wv)          // 294912
#define TPB 128                // scatter tile: 128 pixels/block

// Double-buffered per-batch fp16 accumulator: 2 x 37.7 MB (both L2-resident).
// Invariant: zero at every kernel_launch entry. Initially from static zero
// init; thereafter because transpose_norm_zero re-zeroes every line it reads.
__device__ __align__(256) __half g_scratch[2][(size_t)HWv * Cv];
__device__ __align__(256) float  g_wsum[2][HWv];

__device__ __forceinline__ void red_add_f32(float* p, float v) {
    asm volatile("red.global.add.f32 [%0], %1;" :: "l"(p), "f"(v) : "memory");
}

__device__ __forceinline__ void red_add_f16x2(__half2* p, unsigned v) {
    asm volatile("red.global.add.noftz.f16x2 [%0], %1;" :: "l"(p), "r"(v) : "memory");
}

// ---------------------------------------------------------------------------
// Scatter for ONE batch (identical memory pattern to the 172us champion).
// __ldcs on input streams: evict-first, protects the L2-resident scratch.
// ---------------------------------------------------------------------------
__global__ __launch_bounds__(TPB) void scatter_kernel(
    const float* __restrict__ fmap,    // (C, H, W) for this batch
    const float* __restrict__ flow,    // (2, H, W)
    const float* __restrict__ depth,   // (H, W)
    __half*      __restrict__ scratch, // (HW, C) zeroed
    float*       __restrict__ wsum)    // (HW)    zeroed
{
    __shared__ __half2 s_feat[Cv / 2][TPB + 1];
    __shared__ int     s_idx[TPB];

    int tid = threadIdx.x;
    int p   = blockIdx.x * TPB + tid;       // over HWv
    int y   = p / Wv;
    int x   = p - y * Wv;

    float fx = __ldcs(flow + p);
    float fy = __ldcs(flow + HWv + p);
    float tx = (float)x + fx;
    float ty = (float)y + fy;

    // reference: valid = (tx>=0)&(tx<W-1)&(ty>=0)&(ty<H-1)
    int idx = -1;
    if (tx >= 0.f && tx < (float)(Wv - 1) && ty >= 0.f && ty < (float)(Hv - 1)) {
        int ix = (int)tx;                   // trunc == floor for tx >= 0
        int iy = (int)ty;
        idx = iy * Wv + ix;

        float w = __expf(-__ldcs(depth + p));
        red_add_f32(&wsum[idx], w);

        const float* src = fmap + p;        // stride HWv over c
        #pragma unroll
        for (int c2 = 0; c2 < Cv / 2; c2++) {
            float v0 = __ldcs(src + (size_t)(2 * c2 + 0) * HWv) * w;
            float v1 = __ldcs(src + (size_t)(2 * c2 + 1) * HWv) * w;
            s_feat[c2][tid] = __floats2half2_rn(v0, v1);
        }
    }
    s_idx[tid] = idx;
    __syncthreads();

    int wid  = tid >> 5;
    int lane = tid & 31;

    #pragma unroll 4
    for (int j = 0; j < 32; j++) {
        int px = (wid << 5) + j;
        int ix = s_idx[px];                                   // broadcast read
        if (ix < 0) continue;
        __half2 v = s_feat[lane][px];                         // conflict-free LDS
        __half2* d = reinterpret_cast<__half2*>(scratch + (size_t)ix * Cv) + lane;
        red_add_f16x2(d, *reinterpret_cast<unsigned*>(&v));   // 1 line -> 1 wf, L2-hit
    }
}

// ---------------------------------------------------------------------------
// Transpose (HW,C) fp16 -> (C,HW) f32 for ONE batch, fused normalization,
// mask write, AND scratch re-zero (kills the memset pass; zero stores are
// L2-hit on just-read lines and keep them resident for the next batch).
// Write phase: thread owns 4 consecutive pixels x channel pair -> float4
// stores (4x fewer STG than the scalar version; kernel was issue-bound).
// ---------------------------------------------------------------------------
__global__ __launch_bounds__(256) void transpose_norm_zero_kernel(
    float* __restrict__ out_feat,      // (C, H, W) for this batch
    float* __restrict__ out_mask,      // (H, W)
    __half* __restrict__ scratch,
    float*  __restrict__ wsum)
{
    __shared__ __half2 tile[64][Cv / 2 + 1];   // 64 px x 32 half2 (+pad)
    __shared__ float   s_inv[64];
    __shared__ float   s_msk[64];

    int tid = threadIdx.x;
    int p0  = blockIdx.x * 64;           // 64 pixels per block

    // Load: 64 rows x 8 uint4 chunks, 2 per thread (MLP=2); re-zero each chunk.
    const uint4 z4 = make_uint4(0u, 0u, 0u, 0u);
    #pragma unroll
    for (int i = 0; i < 2; i++) {
        int e   = tid + i * 256;         // 0..511
        int pix = e >> 3;                // 0..63
        int q   = e & 7;                 // 16B chunk in row
        uint4* row = reinterpret_cast<uint4*>(scratch + (size_t)(p0 + pix) * Cv);
        uint4 v = row[q];
        row[q] = z4;                     // restore zero invariant (L2-hit store)
        tile[pix][4 * q + 0] = *reinterpret_cast<__half2*>(&v.x);
        tile[pix][4 * q + 1] = *reinterpret_cast<__half2*>(&v.y);
        tile[pix][4 * q + 2] = *reinterpret_cast<__half2*>(&v.z);
        tile[pix][4 * q + 3] = *reinterpret_cast<__half2*>(&v.w);
    }
    if (tid < 64) {
        float w = wsum[p0 + tid];
        wsum[p0 + tid] = 0.f;            // re-zero
        s_inv[tid] = (w > 0.f) ? (1.f / w) : 1.f;
        s_msk[tid] = (w > 0.f) ? 1.f : 0.f;
    }
    __syncthreads();

    // Write: item e -> (pxg = e&15, c2 = e>>4); 4 consecutive px per item,
    // two float4 streaming stores (channels 2c2, 2c2+1).
    #pragma unroll
    for (int i = 0; i < 2; i++) {
        int e   = tid + i * 256;         // 0..511
        int px0 = (e & 15) * 4;
        int c2  = e >> 4;                // 0..31

        float2 f0 = __half22float2(tile[px0 + 0][c2]);
        float2 f1 = __half22float2(tile[px0 + 1][c2]);
        float2 f2 = __half22float2(tile[px0 + 2][c2]);
        float2 f3 = __half22float2(tile[px0 + 3][c2]);
        float i0 = s_inv[px0 + 0], i1 = s_inv[px0 + 1];
        float i2 = s_inv[px0 + 2], i3 = s_inv[px0 + 3];

        float4 a = make_float4(f0.x * i0, f1.x * i1, f2.x * i2, f3.x * i3);
        float4 bq = make_float4(f0.y * i0, f1.y * i1, f2.y * i2, f3.y * i3);

        __stcs(reinterpret_cast<float4*>(&out_feat[(size_t)(2 * c2 + 0) * HWv + p0 + px0]), a);
        __stcs(reinterpret_cast<float4*>(&out_feat[(size_t)(2 * c2 + 1) * HWv + p0 + px0]), bq);
    }
    if (tid < 64) {
        __stcs(&out_mask[p0 + tid], s_msk[tid]);
    }
}

// ---------------------------------------------------------------------------
// Launch: two independent batch chains (even on capture stream, odd on a
// second stream), double-buffered scratch, no memsets.
// ---------------------------------------------------------------------------
extern "C" void kernel_launch(void* const* d_in, const int* in_sizes, int n_in,
                              void* d_out, int out_size)
{
    const float* fmap  = (const float*)d_in[0];  // (B, C, H, W)
    const float* flow  = (const float*)d_in[1];  // (B, 2, H, W)
    const float* depth = (const float*)d_in[2];  // (B, 1, H, W)

    float* out_feat = (float*)d_out;                               // (B,C,H,W)
    float* out_mask = out_feat + (size_t)Bv * Cv * HWv;            // (B,1,H,W)

    static cudaStream_t s1 = nullptr;
    static cudaEvent_t  eFork = nullptr, eJoin = nullptr;
    if (s1 == nullptr) {
        cudaStreamCreateWithFlags(&s1, cudaStreamNonBlocking);
        cudaEventCreateWithFlags(&eFork, cudaEventDisableTiming);
        cudaEventCreateWithFlags(&eJoin, cudaEventDisableTiming);
    }

    void* sc_ptr = nullptr;
    void* ws_ptr = nullptr;
    cudaGetSymbolAddress(&sc_ptr, g_scratch);
    cudaGetSymbolAddress(&ws_ptr, g_wsum);
    __half* sc = (__half*)sc_ptr;
    float*  ws = (float*)ws_ptr;

    // Fork: odd-batch chain joins the capture dependency graph via event.
    cudaEventRecord(eFork, 0);
    cudaStreamWaitEvent(s1, eFork, 0);

    for (int b = 0; b < Bv; b++) {
        cudaStream_t st  = (b & 1) ? s1 : 0;
        int          buf = b & 1;
        __half* scb = sc + (size_t)buf * HWv * Cv;
        float*  wsb = ws + (size_t)buf * HWv;

        scatter_kernel<<<HWv / TPB, TPB, 0, st>>>(
            fmap  + (size_t)b * Cv * HWv,
            flow  + (size_t)b * 2 * HWv,
            depth + (size_t)b * HWv,
            scb, wsb);

        transpose_norm_zero_kernel<<<HWv / 64, 256, 0, st>>>(
            out_feat + (size_t)b * Cv * HWv,
            out_mask + (size_t)b * HWv,
            scb, wsb);
    }

    // Join: capture stream waits for the odd-batch chain.
    cudaEventRecord(eJoin, s1);
    cudaStreamWaitEvent(0, eJoin, 0);
}

// round 16
// speedup vs baseline: 2.6824x; 2.6824x over previous
#include <cuda_runtime.h>
#include <cuda_fp16.h>
#include <cstdint>

// Problem shape (fixed by the dataset)
#define Bv  4
#define Cv  64
#define Hv  384
#define Wv  768
#define HWv (Hv * Wv)          // 294912
#define TPB 128                // scatter tile: 128 pixels/block

// Double-buffered per-batch fp16 accumulator: 2 x 37.7 MB (both L2-resident).
// Zeroed by cudaMemsetAsync before each batch (NO in-kernel rezero: the
// read+zero-store-same-line pattern measurably serializes -- R7/R15 evidence).
__device__ __align__(256) __half g_scratch[2][(size_t)HWv * Cv];
__device__ __align__(256) float  g_wsum[2][HWv];

__device__ __forceinline__ void red_add_f32(float* p, float v) {
    asm volatile("red.global.add.f32 [%0], %1;" :: "l"(p), "f"(v) : "memory");
}

__device__ __forceinline__ void red_add_f16x2(__half2* p, unsigned v) {
    asm volatile("red.global.add.noftz.f16x2 [%0], %1;" :: "l"(p), "r"(v) : "memory");
}

// ---------------------------------------------------------------------------
// Scatter for ONE batch (memory pattern identical to the 172us champion).
// __ldcs on input streams: evict-first, protects the L2-resident scratch.
// ---------------------------------------------------------------------------
__global__ __launch_bounds__(TPB) void scatter_kernel(
    const float* __restrict__ fmap,    // (C, H, W) for this batch
    const float* __restrict__ flow,    // (2, H, W)
    const float* __restrict__ depth,   // (H, W)
    __half*      __restrict__ scratch, // (HW, C) zeroed
    float*       __restrict__ wsum)    // (HW)    zeroed
{
    __shared__ __half2 s_feat[Cv / 2][TPB + 1];
    __shared__ int     s_idx[TPB];

    int tid = threadIdx.x;
    int p   = blockIdx.x * TPB + tid;       // over HWv
    int y   = p / Wv;
    int x   = p - y * Wv;

    float fx = __ldcs(flow + p);
    float fy = __ldcs(flow + HWv + p);
    float tx = (float)x + fx;
    float ty = (float)y + fy;

    // reference: valid = (tx>=0)&(tx<W-1)&(ty>=0)&(ty<H-1)
    int idx = -1;
    if (tx >= 0.f && tx < (float)(Wv - 1) && ty >= 0.f && ty < (float)(Hv - 1)) {
        int ix = (int)tx;                   // trunc == floor for tx >= 0
        int iy = (int)ty;
        idx = iy * Wv + ix;

        float w = __expf(-__ldcs(depth + p));
        red_add_f32(&wsum[idx], w);

        const float* src = fmap + p;        // stride HWv over c
        #pragma unroll
        for (int c2 = 0; c2 < Cv / 2; c2++) {
            float v0 = __ldcs(src + (size_t)(2 * c2 + 0) * HWv) * w;
            float v1 = __ldcs(src + (size_t)(2 * c2 + 1) * HWv) * w;
            s_feat[c2][tid] = __floats2half2_rn(v0, v1);
        }
    }
    s_idx[tid] = idx;
    __syncthreads();

    int wid  = tid >> 5;
    int lane = tid & 31;

    #pragma unroll 4
    for (int j = 0; j < 32; j++) {
        int px = (wid << 5) + j;
        int ix = s_idx[px];                                   // broadcast read
        if (ix < 0) continue;
        __half2 v = s_feat[lane][px];                         // conflict-free LDS
        __half2* d = reinterpret_cast<__half2*>(scratch + (size_t)ix * Cv) + lane;
        red_add_f16x2(d, *reinterpret_cast<unsigned*>(&v));   // 1 line -> 1 wf, L2-hit
    }
}

// ---------------------------------------------------------------------------
// Transpose (HW,C) fp16 -> (C,HW) f32 for ONE batch, fused normalization +
// mask. R14 load phase (pure reads, MLP=2, NO rezero). Write phase: thread
// owns 4 consecutive pixels x channel pair -> float4 streaming stores
// (4x fewer STG; R14's write phase was issue-bound at 28%).
// ---------------------------------------------------------------------------
__global__ __launch_bounds__(256) void transpose_norm_kernel(
    float* __restrict__ out_feat,      // (C, H, W) for this batch
    float* __restrict__ out_mask,      // (H, W)
    const __half* __restrict__ scratch,
    const float*  __restrict__ wsum)
{
    __shared__ __half2 tile[64][Cv / 2 + 1];   // 64 px x 32 half2 (+pad)
    __shared__ float   s_inv[64];
    __shared__ float   s_msk[64];

    int tid = threadIdx.x;
    int p0  = blockIdx.x * 64;           // 64 pixels per block

    // Load: 64 rows x 8 uint4 chunks, 2 per thread (independent -> MLP=2).
    #pragma unroll
    for (int i = 0; i < 2; i++) {
        int e   = tid + i * 256;         // 0..511
        int pix = e >> 3;                // 0..63
        int q   = e & 7;                 // 16B chunk in row
        const uint4* row = reinterpret_cast<const uint4*>(
            scratch + (size_t)(p0 + pix) * Cv);
        uint4 v = row[q];
        tile[pix][4 * q + 0] = *reinterpret_cast<__half2*>(&v.x);
        tile[pix][4 * q + 1] = *reinterpret_cast<__half2*>(&v.y);
        tile[pix][4 * q + 2] = *reinterpret_cast<__half2*>(&v.z);
        tile[pix][4 * q + 3] = *reinterpret_cast<__half2*>(&v.w);
    }
    if (tid < 64) {
        float w = wsum[p0 + tid];
        s_inv[tid] = (w > 0.f) ? (1.f / w) : 1.f;
        s_msk[tid] = (w > 0.f) ? 1.f : 0.f;
    }
    __syncthreads();

    // Write: item e -> (px0 = (e&15)*4, c2 = e>>4); two float4 stores
    // (channels 2c2 and 2c2+1) over 4 consecutive pixels.
    #pragma unroll
    for (int i = 0; i < 2; i++) {
        int e   = tid + i * 256;         // 0..511
        int px0 = (e & 15) * 4;
        int c2  = e >> 4;                // 0..31

        float2 f0 = __half22float2(tile[px0 + 0][c2]);
        float2 f1 = __half22float2(tile[px0 + 1][c2]);
        float2 f2 = __half22float2(tile[px0 + 2][c2]);
        float2 f3 = __half22float2(tile[px0 + 3][c2]);
        float i0 = s_inv[px0 + 0], i1 = s_inv[px0 + 1];
        float i2 = s_inv[px0 + 2], i3 = s_inv[px0 + 3];

        float4 a = make_float4(f0.x * i0, f1.x * i1, f2.x * i2, f3.x * i3);
        float4 bq = make_float4(f0.y * i0, f1.y * i1, f2.y * i2, f3.y * i3);

        __stcs(reinterpret_cast<float4*>(&out_feat[(size_t)(2 * c2 + 0) * HWv + p0 + px0]), a);
        __stcs(reinterpret_cast<float4*>(&out_feat[(size_t)(2 * c2 + 1) * HWv + p0 + px0]), bq);
    }
    if (tid < 64) {
        __stcs(&out_mask[p0 + tid], s_msk[tid]);
    }
}

// ---------------------------------------------------------------------------
// Launch: two independent batch chains (even on capture stream, odd on a
// side stream), double-buffered scratch, memsets retained per batch.
// ---------------------------------------------------------------------------
extern "C" void kernel_launch(void* const* d_in, const int* in_sizes, int n_in,
                              void* d_out, int out_size)
{
    const float* fmap  = (const float*)d_in[0];  // (B, C, H, W)
    const float* flow  = (const float*)d_in[1];  // (B, 2, H, W)
    const float* depth = (const float*)d_in[2];  // (B, 1, H, W)

    float* out_feat = (float*)d_out;                               // (B,C,H,W)
    float* out_mask = out_feat + (size_t)Bv * Cv * HWv;            // (B,1,H,W)

    static cudaStream_t s1 = nullptr;
    static cudaEvent_t  eFork = nullptr, eJoin = nullptr;
    if (s1 == nullptr) {
        cudaStreamCreateWithFlags(&s1, cudaStreamNonBlocking);
        cudaEventCreateWithFlags(&eFork, cudaEventDisableTiming);
        cudaEventCreateWithFlags(&eJoin, cudaEventDisableTiming);
    }

    void* sc_ptr = nullptr;
    void* ws_ptr = nullptr;
    cudaGetSymbolAddress(&sc_ptr, g_scratch);
    cudaGetSymbolAddress(&ws_ptr, g_wsum);
    __half* sc = (__half*)sc_ptr;
    float*  ws = (float*)ws_ptr;

    // Fork: side stream joins the capture dependency graph via event.
    cudaEventRecord(eFork, 0);
    cudaStreamWaitEvent(s1, eFork, 0);

    for (int b = 0; b < Bv; b++) {
        cudaStream_t st  = (b & 1) ? s1 : 0;
        int          buf = b & 1;
        __half* scb = sc + (size_t)buf * HWv * Cv;
        float*  wsb = ws + (size_t)buf * HWv;

        cudaMemsetAsync(scb, 0, (size_t)HWv * Cv * sizeof(__half), st);
        cudaMemsetAsync(wsb, 0, (size_t)HWv * sizeof(float), st);

        scatter_kernel<<<HWv / TPB, TPB, 0, st>>>(
            fmap  + (size_t)b * Cv * HWv,
            flow  + (size_t)b * 2 * HWv,
            depth + (size_t)b * HWv,
            scb, wsb);

        transpose_norm_kernel<<<HWv / 64, 256, 0, st>>>(
            out_feat + (size_t)b * Cv * HWv,
            out_mask + (size_t)b * HWv,
            scb, wsb);
    }

    // Join: capture stream waits for the side chain.
    cudaEventRecord(eJoin, s1);
    cudaStreamWaitEvent(0, eJoin, 0);
}